// round 2
// baseline (speedup 1.0000x reference)
#include <cuda_runtime.h>
#include <cstdint>

// Conv2d: x(128,256,256) * w(256,128,3,3) + b(256) -> out(256,256,256)
// stride 1, pad 1, fp32. Implicit-GEMM direct conv using packed fma.rn.f32x2.

#define C_IN   128
#define C_OUT  256
#define HW     256
#define TILE_H 16
#define TILE_W 16
#define TILE_OC 64
#define CI_CHUNK 8
#define XROWS 18          // 16 + 2 halo
#define XSTR  21          // padded row stride (floats) -> <=2-way bank conflicts

__global__ __launch_bounds__(256, 2)
void conv3x3_f32x2_kernel(const float* __restrict__ x,
                          const float* __restrict__ w,
                          const float* __restrict__ bias,
                          float* __restrict__ out)
{
    __shared__ float sx[CI_CHUNK * XROWS * XSTR];                 // 12,096 B
    __shared__ unsigned long long sw[TILE_OC * CI_CHUNK * 9];     // 36,864 B

    const int tid  = threadIdx.x;
    const int oc_g = tid >> 5;       // 0..7 : warp == one oc group (uniform w loads)
    const int sp   = tid & 31;
    const int rg   = sp >> 2;        // 0..7 : row group (covers rows rg and rg+8)
    const int cg   = sp & 3;         // 0..3 : col group
    const int c0   = cg << 2;        // 4 contiguous output cols

    const int bx  = blockIdx.x;
    const int by  = blockIdx.y;
    const int oc0 = blockIdx.z * TILE_OC;
    const int gx0 = bx * TILE_W - 1;  // input tile origin (includes -1 pad shift)
    const int gy0 = by * TILE_H - 1;

    // acc[oc][cc] : f32x2 pair = (out[rowA=rg], out[rowB=rg+8]) for col c0+cc
    unsigned long long acc[8][4];
#pragma unroll
    for (int i = 0; i < 8; i++)
#pragma unroll
        for (int j = 0; j < 4; j++) acc[i][j] = 0ull;

    for (int cb = 0; cb < C_IN; cb += CI_CHUNK) {
        // ---- load x halo tile (CI_CHUNK x 18 x 18), zero-fill out of bounds ----
        for (int idx = tid; idx < CI_CHUNK * XROWS * XROWS; idx += 256) {
            int ci  = idx / (XROWS * XROWS);
            int rem = idx - ci * (XROWS * XROWS);
            int r   = rem / XROWS;
            int c   = rem - r * XROWS;
            int gy  = gy0 + r;
            int gx  = gx0 + c;
            float v = 0.0f;
            if ((unsigned)gy < (unsigned)HW && (unsigned)gx < (unsigned)HW)
                v = x[(cb + ci) * (HW * HW) + gy * HW + gx];
            sx[(ci * XROWS + r) * XSTR + c] = v;
        }
        // ---- load weight tile, duplicated into (w,w) 64-bit pairs ----
        for (int idx = tid; idx < TILE_OC * CI_CHUNK * 9; idx += 256) {
            int oc  = idx / (CI_CHUNK * 9);
            int rem = idx - oc * (CI_CHUNK * 9);     // ci*9 + k
            float wv = w[(oc0 + oc) * (C_IN * 9) + cb * 9 + rem];
            unsigned int b = __float_as_uint(wv);
            sw[idx] = ((unsigned long long)b << 32) | (unsigned long long)b;
        }
        __syncthreads();

#pragma unroll 1
        for (int ci = 0; ci < CI_CHUNK; ci++) {
#pragma unroll
            for (int ky = 0; ky < 3; ky++) {
                const float* rA = &sx[(ci * XROWS + rg + ky) * XSTR + c0];
                const float* rB = rA + 8 * XSTR;
                unsigned long long p[6];
#pragma unroll
                for (int j = 0; j < 6; j++) {
                    float a = rA[j];
                    float b = rB[j];
                    asm("mov.b64 %0, {%1, %2};" : "=l"(p[j]) : "f"(a), "f"(b));
                }
#pragma unroll
                for (int kx = 0; kx < 3; kx++) {
#pragma unroll
                    for (int oc = 0; oc < 8; oc++) {
                        unsigned long long wp =
                            sw[((oc_g * 8 + oc) * CI_CHUNK + ci) * 9 + ky * 3 + kx];
#pragma unroll
                        for (int cc = 0; cc < 4; cc++) {
                            asm("fma.rn.f32x2 %0, %1, %2, %3;"
                                : "=l"(acc[oc][cc])
                                : "l"(p[kx + cc]), "l"(wp), "l"(acc[oc][cc]));
                        }
                    }
                }
            }
        }
        __syncthreads();
    }

    // ---- epilogue: unpack pairs, add bias, vectorized stores ----
    const int oy = by * TILE_H + rg;
    const int ox = bx * TILE_W + c0;
#pragma unroll
    for (int oc = 0; oc < 8; oc++) {
        const int o  = oc0 + oc_g * 8 + oc;
        const float bv = bias[o];
        float* po = &out[o * (HW * HW) + oy * HW + ox];
        float lo0, hi0, lo1, hi1, lo2, hi2, lo3, hi3;
        asm("mov.b64 {%0, %1}, %2;" : "=f"(lo0), "=f"(hi0) : "l"(acc[oc][0]));
        asm("mov.b64 {%0, %1}, %2;" : "=f"(lo1), "=f"(hi1) : "l"(acc[oc][1]));
        asm("mov.b64 {%0, %1}, %2;" : "=f"(lo2), "=f"(hi2) : "l"(acc[oc][2]));
        asm("mov.b64 {%0, %1}, %2;" : "=f"(lo3), "=f"(hi3) : "l"(acc[oc][3]));
        float4 vlo = make_float4(lo0 + bv, lo1 + bv, lo2 + bv, lo3 + bv);
        float4 vhi = make_float4(hi0 + bv, hi1 + bv, hi2 + bv, hi3 + bv);
        *reinterpret_cast<float4*>(po)            = vlo;   // row rg
        *reinterpret_cast<float4*>(po + 8 * HW)   = vhi;   // row rg+8
    }
}

extern "C" void kernel_launch(void* const* d_in, const int* in_sizes, int n_in,
                              void* d_out, int out_size)
{
    const float* x    = (const float*)d_in[0];   // (128,256,256)
    const float* wgt  = (const float*)d_in[1];   // (256,128,3,3)
    const float* bias = (const float*)d_in[2];   // (256,1,1)
    float* out = (float*)d_out;                  // (256,256,256)

    dim3 grid(HW / TILE_W, HW / TILE_H, C_OUT / TILE_OC);  // (16,16,4)
    conv3x3_f32x2_kernel<<<grid, 256>>>(x, wgt, bias, out);
}

// round 5
// speedup vs baseline: 2.8145x; 2.8145x over previous
#include <cuda_runtime.h>
#include <cuda_bf16.h>
#include <cstdint>

// Conv2d 3x3 pad1: x(128,256,256) * w(256,128,3,3) + b(256) -> out(256,256,256)
// Implicit GEMM via warp-level mma.sync (bf16, 3-pass split for fp32 accuracy).
// M=256 oc, N=65536 px, K=1152. CTA: 128oc x 128px, kChunk=32.

#define HW     256
#define KTOT   1152
#define KC     32
#define NCHUNK 36
#define NTHR   256
#define STR    80            // bytes per smem row (64B data + pad): conflict-free ldmatrix

#define AH_OFF 0
#define AL_OFF 10240
#define BH_OFF 20480
#define BL_OFF 30720
#define SMEM_BYTES 40960

__device__ __forceinline__ uint32_t s2u(const void* p) {
    uint32_t a;
    asm("{ .reg .u64 t; cvta.to.shared.u64 t, %1; cvt.u32.u64 %0, t; }"
        : "=r"(a) : "l"(p));
    return a;
}

#define LDM4(r0, r1, r2, r3, addr)                                         \
    asm volatile("ldmatrix.sync.aligned.m8n8.x4.shared.b16 "               \
                 "{%0,%1,%2,%3}, [%4];"                                    \
                 : "=r"(r0), "=r"(r1), "=r"(r2), "=r"(r3) : "r"(addr))

#define MMA(d, a, b)                                                       \
    asm volatile("mma.sync.aligned.m16n8k16.row.col.f32.bf16.bf16.f32 "    \
                 "{%0,%1,%2,%3}, {%4,%5,%6,%7}, {%8,%9}, {%0,%1,%2,%3};"   \
                 : "+f"((d)[0]), "+f"((d)[1]), "+f"((d)[2]), "+f"((d)[3])  \
                 : "r"((a)[0]), "r"((a)[1]), "r"((a)[2]), "r"((a)[3]),     \
                   "r"((b)[0]), "r"((b)[1]))

__device__ __forceinline__ uint32_t pack2(__nv_bfloat16 lo, __nv_bfloat16 hi) {
    return ((uint32_t)__bfloat16_as_ushort(hi) << 16) |
           (uint32_t)__bfloat16_as_ushort(lo);
}

__global__ __launch_bounds__(NTHR, 2)
void conv3x3_mma_kernel(const float* __restrict__ x,
                        const float* __restrict__ w,
                        const float* __restrict__ bias,
                        float* __restrict__ out)
{
    __shared__ __align__(16) char smem[SMEM_BYTES];
    const uint32_t sb = s2u(smem);

    const int tid  = threadIdx.x;
    const int lane = tid & 31;
    const int wid  = tid >> 5;
    const int wm   = wid >> 2;        // 0..1 : 64-oc warp tile
    const int wn   = wid & 3;         // 0..3 : 32-px warp tile

    const int x0  = blockIdx.x * 128;
    const int y   = blockIdx.y;
    const int oc0 = blockIdx.z * 128;

    // ldmatrix lane address components
    const int a_row = lane & 15;                       // A: row within 16
    const int a_kh  = lane >> 4;                       // A: k half
    const int b_n   = (lane & 7) | ((lane >> 4) << 3); // B: n within 16
    const int b_kh  = (lane >> 3) & 1;                 // B: k half

    float acc[4][4][4];
#pragma unroll
    for (int i = 0; i < 4; i++)
#pragma unroll
        for (int j = 0; j < 4; j++)
#pragma unroll
            for (int q = 0; q < 4; q++) acc[i][j][q] = 0.0f;

    for (int c = 0; c < NCHUNK; c++) {
        __syncthreads();   // previous chunk's mma done before overwriting tiles

        // ---- A: weights 128oc x 32k, fp32 -> bf16 hi/lo ----
#pragma unroll
        for (int i = 0; i < 4; i++) {
            const int idx = tid + i * NTHR;       // 0..1023
            const int row = idx >> 3;
            const int seg = idx & 7;              // 4 k each
            float4 v = *(const float4*)(w + (size_t)(oc0 + row) * KTOT
                                          + c * KC + seg * 4);
            __nv_bfloat16 h0 = __float2bfloat16(v.x);
            __nv_bfloat16 h1 = __float2bfloat16(v.y);
            __nv_bfloat16 h2 = __float2bfloat16(v.z);
            __nv_bfloat16 h3 = __float2bfloat16(v.w);
            __nv_bfloat16 l0 = __float2bfloat16(v.x - __bfloat162float(h0));
            __nv_bfloat16 l1 = __float2bfloat16(v.y - __bfloat162float(h1));
            __nv_bfloat16 l2 = __float2bfloat16(v.z - __bfloat162float(h2));
            __nv_bfloat16 l3 = __float2bfloat16(v.w - __bfloat162float(h3));
            uint2 hp = make_uint2(pack2(h0, h1), pack2(h2, h3));
            uint2 lp = make_uint2(pack2(l0, l1), pack2(l2, l3));
            *(uint2*)(smem + AH_OFF + row * STR + seg * 8) = hp;
            *(uint2*)(smem + AL_OFF + row * STR + seg * 8) = lp;
        }

        // ---- B: im2col 128px x 32k, fp32 -> bf16 hi/lo ----
#pragma unroll
        for (int i = 0; i < 16; i++) {
            const int idx = tid + i * NTHR;       // 0..4095
            const int j   = idx >> 7;             // k within chunk
            const int p   = idx & 127;
            const int kg  = c * KC + j;
            const int ci  = kg / 9;
            const int tp  = kg - ci * 9;
            const int ky  = tp / 3;
            const int kx  = tp - ky * 3;
            const int gy  = y + ky - 1;
            const int gx  = x0 + p + kx - 1;
            float v = 0.0f;
            if ((unsigned)gy < (unsigned)HW && (unsigned)gx < (unsigned)HW)
                v = __ldg(x + ci * (HW * HW) + gy * HW + gx);
            __nv_bfloat16 hb = __float2bfloat16(v);
            __nv_bfloat16 lb = __float2bfloat16(v - __bfloat162float(hb));
            *(__nv_bfloat16*)(smem + BH_OFF + p * STR + j * 2) = hb;
            *(__nv_bfloat16*)(smem + BL_OFF + p * STR + j * 2) = lb;
        }

        __syncthreads();

        // ---- compute: 2 k16 steps, 3 passes (hh, lh, hl) ----
#pragma unroll
        for (int ks = 0; ks < 2; ks++) {
            uint32_t ah[4][4], al[4][4], bb[2][4];

#pragma unroll
            for (int mf = 0; mf < 4; mf++) {
                const uint32_t ao =
                    (uint32_t)((wm * 64 + mf * 16 + a_row) * STR
                               + ks * 32 + a_kh * 16);
                LDM4(ah[mf][0], ah[mf][1], ah[mf][2], ah[mf][3],
                     sb + AH_OFF + ao);
                LDM4(al[mf][0], al[mf][1], al[mf][2], al[mf][3],
                     sb + AL_OFF + ao);
            }
#pragma unroll
            for (int bp = 0; bp < 2; bp++) {
                const uint32_t bo =
                    (uint32_t)((wn * 32 + bp * 16 + b_n) * STR
                               + ks * 32 + b_kh * 16);
                LDM4(bb[bp][0], bb[bp][1], bb[bp][2], bb[bp][3],
                     sb + BH_OFF + bo);
            }

            // pass 1: Ahi * Bhi     pass 2: Alo * Bhi
#pragma unroll
            for (int mf = 0; mf < 4; mf++)
#pragma unroll
                for (int nf = 0; nf < 4; nf++) {
                    uint32_t bfrag[2] = { bb[nf >> 1][(nf & 1) * 2 + 0],
                                          bb[nf >> 1][(nf & 1) * 2 + 1] };
                    MMA(acc[mf][nf], ah[mf], bfrag);
                    MMA(acc[mf][nf], al[mf], bfrag);
                }

            // reload B as lo
#pragma unroll
            for (int bp = 0; bp < 2; bp++) {
                const uint32_t bo =
                    (uint32_t)((wn * 32 + bp * 16 + b_n) * STR
                               + ks * 32 + b_kh * 16);
                LDM4(bb[bp][0], bb[bp][1], bb[bp][2], bb[bp][3],
                     sb + BL_OFF + bo);
            }

            // pass 3: Ahi * Blo
#pragma unroll
            for (int mf = 0; mf < 4; mf++)
#pragma unroll
                for (int nf = 0; nf < 4; nf++) {
                    uint32_t bfrag[2] = { bb[nf >> 1][(nf & 1) * 2 + 0],
                                          bb[nf >> 1][(nf & 1) * 2 + 1] };
                    MMA(acc[mf][nf], ah[mf], bfrag);
                }
        }
    }

    // ---- epilogue: acc + bias -> out ----
#pragma unroll
    for (int mf = 0; mf < 4; mf++) {
        const int ocb = oc0 + wm * 64 + mf * 16 + (lane >> 2);
        const float bv0 = bias[ocb];
        const float bv1 = bias[ocb + 8];
#pragma unroll
        for (int nf = 0; nf < 4; nf++) {
            const int px = wn * 32 + nf * 8 + (lane & 3) * 2;
            float* p0 = out + (size_t)ocb * (HW * HW) + (size_t)y * HW + x0 + px;
            float2 v0 = make_float2(acc[mf][nf][0] + bv0, acc[mf][nf][1] + bv0);
            float2 v1 = make_float2(acc[mf][nf][2] + bv1, acc[mf][nf][3] + bv1);
            *(float2*)p0 = v0;
            *(float2*)(p0 + 8 * (HW * HW)) = v1;
        }
    }
}

extern "C" void kernel_launch(void* const* d_in, const int* in_sizes, int n_in,
                              void* d_out, int out_size)
{
    const float* x    = (const float*)d_in[0];   // (128,256,256)
    const float* wgt  = (const float*)d_in[1];   // (256,128,3,3)
    const float* bias = (const float*)d_in[2];   // (256,1,1)
    float* out = (float*)d_out;                  // (256,256,256)

    dim3 grid(HW / 128, HW, 2);   // (2, 256, 2)
    conv3x3_mma_kernel<<<grid, NTHR>>>(x, wgt, bias, out);
}

// round 6
// speedup vs baseline: 4.8592x; 1.7265x over previous
#include <cuda_runtime.h>
#include <cuda_bf16.h>
#include <cstdint>

// Conv2d 3x3 pad1: x(128,256,256) * w(256,128,3,3) + b(256) -> out(256,256,256)
// Tap-decomposed implicit GEMM on mma.sync bf16 (3-pass hi/lo split = fp32 acc).
// Pre-pass converts x -> HWC bf16 hi/lo scratch and w -> [tap][oc][ci] hi/lo.
// Main kernel: per 32-ci chunk load shifted-window x tile ONCE, reuse for 9 taps.

#define HW    256
#define CI    128
#define OC    256
#define NTHR  256
#define STR   80                    // smem row stride (64B data + pad, 16B aligned)
#define PLANE (130 * STR)           // 10400 B : one gy plane (130 gx rows)
#define XH_OFF 0
#define XL_OFF (3 * PLANE)          // 31200
#define A_BASE (6 * PLANE)          // 62400
#define A_TILE 10240                // 128 oc rows x 80B
#define AOFF(buf, split) (A_BASE + (buf) * 2 * A_TILE + (split) * A_TILE)
#define SMEM_BYTES (A_BASE + 4 * A_TILE)   // 103360

// ---- global scratch (pre-split bf16) ----
__device__ __nv_bfloat16 g_xhi[HW * HW * CI];    // [y][x][ci]
__device__ __nv_bfloat16 g_xlo[HW * HW * CI];
__device__ __nv_bfloat16 g_whi[9 * OC * CI];     // [tap][oc][ci]
__device__ __nv_bfloat16 g_wlo[9 * OC * CI];

__device__ __forceinline__ uint32_t s2u(const void* p) {
    uint32_t a;
    asm("{ .reg .u64 t; cvta.to.shared.u64 t, %1; cvt.u32.u64 %0, t; }"
        : "=r"(a) : "l"(p));
    return a;
}

#define CP16(sa, ga, sz)                                                   \
    asm volatile("cp.async.cg.shared.global [%0], [%1], 16, %2;"           \
                 :: "r"(sa), "l"(ga), "r"(sz) : "memory")
#define CP_COMMIT()  asm volatile("cp.async.commit_group;" ::: "memory")
#define CP_WAIT0()   asm volatile("cp.async.wait_group 0;" ::: "memory")

#define LDM4(r0, r1, r2, r3, addr)                                         \
    asm volatile("ldmatrix.sync.aligned.m8n8.x4.shared.b16 "               \
                 "{%0,%1,%2,%3}, [%4];"                                    \
                 : "=r"(r0), "=r"(r1), "=r"(r2), "=r"(r3) : "r"(addr))

#define MMA(d, a, b)                                                       \
    asm volatile("mma.sync.aligned.m16n8k16.row.col.f32.bf16.bf16.f32 "    \
                 "{%0,%1,%2,%3}, {%4,%5,%6,%7}, {%8,%9}, {%0,%1,%2,%3};"   \
                 : "+f"((d)[0]), "+f"((d)[1]), "+f"((d)[2]), "+f"((d)[3])  \
                 : "r"((a)[0]), "r"((a)[1]), "r"((a)[2]), "r"((a)[3]),     \
                   "r"((b)[0]), "r"((b)[1]))

// ======================= pre-pass: x CHW fp32 -> HWC bf16 hi/lo =============
__global__ __launch_bounds__(256)
void prep_x_kernel(const float* __restrict__ x)
{
    __shared__ float sx[CI * 65];            // [ci][px], pad 65
    const int tid = threadIdx.x;
    const int px0 = blockIdx.x * 64;
    const int y   = blockIdx.y;

#pragma unroll
    for (int it = 0; it < 32; it++) {        // 128 ci x 64 px
        const int idx = it * 256 + tid;
        const int ci  = idx >> 6;
        const int px  = idx & 63;
        sx[ci * 65 + px] = x[ci * (HW * HW) + y * HW + px0 + px];
    }
    __syncthreads();

#pragma unroll
    for (int it = 0; it < 8; it++) {         // 64 px x 32 ci-groups(4)
        const int idx = it * 256 + tid;
        const int px  = idx >> 5;
        const int ci  = (idx & 31) * 4;
        ushort4 h, l;
        float v0 = sx[(ci + 0) * 65 + px];
        float v1 = sx[(ci + 1) * 65 + px];
        float v2 = sx[(ci + 2) * 65 + px];
        float v3 = sx[(ci + 3) * 65 + px];
        __nv_bfloat16 h0 = __float2bfloat16(v0), h1 = __float2bfloat16(v1);
        __nv_bfloat16 h2 = __float2bfloat16(v2), h3 = __float2bfloat16(v3);
        h.x = __bfloat16_as_ushort(h0); h.y = __bfloat16_as_ushort(h1);
        h.z = __bfloat16_as_ushort(h2); h.w = __bfloat16_as_ushort(h3);
        l.x = __bfloat16_as_ushort(__float2bfloat16(v0 - __bfloat162float(h0)));
        l.y = __bfloat16_as_ushort(__float2bfloat16(v1 - __bfloat162float(h1)));
        l.z = __bfloat16_as_ushort(__float2bfloat16(v2 - __bfloat162float(h2)));
        l.w = __bfloat16_as_ushort(__float2bfloat16(v3 - __bfloat162float(h3)));
        const size_t o = ((size_t)(y * HW + px0 + px) * CI + ci);
        *(ushort4*)(g_xhi + o) = h;
        *(ushort4*)(g_xlo + o) = l;
    }
}

// ============= pre-pass: w (oc,ci,3,3) fp32 -> [tap][oc][ci] bf16 hi/lo =====
__global__ __launch_bounds__(256)
void prep_w_kernel(const float* __restrict__ w)
{
    const int o = blockIdx.x * 256 + threadIdx.x;   // 9*256*128 = 294912
    const int tap = o >> 15;
    const int oc  = (o >> 7) & 255;
    const int ci  = o & 127;
    const float v = w[(oc * CI + ci) * 9 + tap];
    const __nv_bfloat16 hb = __float2bfloat16(v);
    g_whi[o] = hb;
    g_wlo[o] = __float2bfloat16(v - __bfloat162float(hb));
}

// =========================== main GEMM kernel ===============================
__global__ __launch_bounds__(NTHR, 2)
void conv3x3_tap_kernel(const float* __restrict__ bias,
                        float* __restrict__ out)
{
    extern __shared__ __align__(16) char smem[];
    const uint32_t sb = s2u(smem);

    const int tid  = threadIdx.x;
    const int lane = tid & 31;
    const int wid  = tid >> 5;
    const int wm   = wid >> 2;        // 0..1 : 64-oc warp tile
    const int wn   = wid & 3;         // 0..3 : 32-px warp tile

    const int x0  = blockIdx.x * 128;
    const int y   = blockIdx.y;
    const int oc0 = blockIdx.z * 128;

    const int a_row = lane & 15;
    const int a_kh  = lane >> 4;
    const int b_n   = (lane & 7) | ((lane >> 4) << 3);
    const int b_kh  = (lane >> 3) & 1;

    float acc[4][4][4];
#pragma unroll
    for (int i = 0; i < 4; i++)
#pragma unroll
        for (int j = 0; j < 4; j++)
#pragma unroll
            for (int q = 0; q < 4; q++) acc[i][j][q] = 0.0f;

#pragma unroll 1
    for (int cb = 0; cb < 4; cb++) {
        const int ci0 = cb * 32;

        // ---- stage x chunk: 3 planes x 130 rows x 32 ci, hi+lo ----
#pragma unroll 1
        for (int i = tid; i < 1560; i += NTHR) {      // 390 rows * 4 x 16B
            const int q   = i & 3;
            const int row = i >> 2;                    // 0..389
            const int ky  = row / 130;
            const int gxl = row - ky * 130;
            const int gy  = y + ky - 1;
            const int gx  = x0 + gxl - 1;
            const uint32_t ok =
                ((unsigned)gy < (unsigned)HW && (unsigned)gx < (unsigned)HW)
                ? 16u : 0u;
            const int gyc = ok ? gy : 0;
            const int gxc = ok ? gx : 0;
            const size_t go = ((size_t)(gyc * HW + gxc) * CI + ci0) * 2 + q * 16;
            const uint32_t sa = sb + XH_OFF + ky * PLANE + gxl * STR + q * 16;
            CP16(sa, (const char*)g_xhi + go, ok);
            CP16(sa + XL_OFF, (const char*)g_xlo + go, ok);
        }
        // ---- stage A tap 0 into buf 0 ----
#pragma unroll 1
        for (int i = tid; i < 512; i += NTHR) {
            const int q  = i & 3;
            const int oc = i >> 2;
            const size_t go = ((size_t)(oc0 + oc) * CI + ci0) * 2 + q * 16;
            CP16(sb + AOFF(0, 0) + oc * STR + q * 16, (const char*)g_whi + go, 16u);
            CP16(sb + AOFF(0, 1) + oc * STR + q * 16, (const char*)g_wlo + go, 16u);
        }
        CP_COMMIT();
        CP_WAIT0();
        __syncthreads();

#pragma unroll 1
        for (int tap = 0; tap < 9; tap++) {
            // prefetch next tap's A into the other buffer
            if (tap < 8) {
                const int nb = (tap + 1) & 1;
#pragma unroll 1
                for (int i = tid; i < 512; i += NTHR) {
                    const int q  = i & 3;
                    const int oc = i >> 2;
                    const size_t go =
                        ((size_t)((tap + 1) * OC + oc0 + oc) * CI + ci0) * 2 + q * 16;
                    CP16(sb + AOFF(nb, 0) + oc * STR + q * 16,
                         (const char*)g_whi + go, 16u);
                    CP16(sb + AOFF(nb, 1) + oc * STR + q * 16,
                         (const char*)g_wlo + go, 16u);
                }
                CP_COMMIT();
            }

            // ---- compute this tap ----
            const int ky = tap / 3;
            const int kx = tap - ky * 3;
            const int ab = tap & 1;
            const uint32_t xbase = sb + XH_OFF + ky * PLANE + kx * STR;

#pragma unroll
            for (int ks = 0; ks < 2; ks++) {
                uint32_t ah[4][4], al[4][4], bb[2][4];

#pragma unroll
                for (int mf = 0; mf < 4; mf++) {
                    const uint32_t ao =
                        (uint32_t)((wm * 64 + mf * 16 + a_row) * STR
                                   + ks * 32 + a_kh * 16);
                    LDM4(ah[mf][0], ah[mf][1], ah[mf][2], ah[mf][3],
                         sb + AOFF(ab, 0) + ao);
                    LDM4(al[mf][0], al[mf][1], al[mf][2], al[mf][3],
                         sb + AOFF(ab, 1) + ao);
                }
#pragma unroll
                for (int bp = 0; bp < 2; bp++) {
                    const uint32_t bo =
                        (uint32_t)((wn * 32 + bp * 16 + b_n) * STR
                                   + ks * 32 + b_kh * 16);
                    LDM4(bb[bp][0], bb[bp][1], bb[bp][2], bb[bp][3],
                         xbase + bo);
                }
                // pass 1: Ahi*Bhi    pass 2: Alo*Bhi
#pragma unroll
                for (int mf = 0; mf < 4; mf++)
#pragma unroll
                    for (int nf = 0; nf < 4; nf++) {
                        uint32_t bf[2] = { bb[nf >> 1][(nf & 1) * 2 + 0],
                                           bb[nf >> 1][(nf & 1) * 2 + 1] };
                        MMA(acc[mf][nf], ah[mf], bf);
                        MMA(acc[mf][nf], al[mf], bf);
                    }
                // reload B as lo, pass 3: Ahi*Blo
#pragma unroll
                for (int bp = 0; bp < 2; bp++) {
                    const uint32_t bo =
                        (uint32_t)((wn * 32 + bp * 16 + b_n) * STR
                                   + ks * 32 + b_kh * 16);
                    LDM4(bb[bp][0], bb[bp][1], bb[bp][2], bb[bp][3],
                         xbase + XL_OFF + bo);
                }
#pragma unroll
                for (int mf = 0; mf < 4; mf++)
#pragma unroll
                    for (int nf = 0; nf < 4; nf++) {
                        uint32_t bf[2] = { bb[nf >> 1][(nf & 1) * 2 + 0],
                                           bb[nf >> 1][(nf & 1) * 2 + 1] };
                        MMA(acc[mf][nf], ah[mf], bf);
                    }
            }

            if (tap < 8) {
                CP_WAIT0();
                __syncthreads();
            }
        }
        __syncthreads();   // protect x tile before next chunk's staging
    }

    // ---- epilogue: acc + bias -> out ----
#pragma unroll
    for (int mf = 0; mf < 4; mf++) {
        const int ocb = oc0 + wm * 64 + mf * 16 + (lane >> 2);
        const float bv0 = bias[ocb];
        const float bv1 = bias[ocb + 8];
#pragma unroll
        for (int nf = 0; nf < 4; nf++) {
            const int px = wn * 32 + nf * 8 + (lane & 3) * 2;
            float* p0 = out + (size_t)ocb * (HW * HW) + (size_t)y * HW + x0 + px;
            float2 v0 = make_float2(acc[mf][nf][0] + bv0, acc[mf][nf][1] + bv0);
            float2 v1 = make_float2(acc[mf][nf][2] + bv1, acc[mf][nf][3] + bv1);
            *(float2*)p0 = v0;
            *(float2*)(p0 + 8 * (HW * HW)) = v1;
        }
    }
}

extern "C" void kernel_launch(void* const* d_in, const int* in_sizes, int n_in,
                              void* d_out, int out_size)
{
    const float* x    = (const float*)d_in[0];   // (128,256,256)
    const float* wgt  = (const float*)d_in[1];   // (256,128,3,3)
    const float* bias = (const float*)d_in[2];   // (256,1,1)
    float* out = (float*)d_out;                  // (256,256,256)

    prep_x_kernel<<<dim3(HW / 64, HW), 256>>>(x);
    prep_w_kernel<<<dim3(9 * OC * CI / 256), 256>>>(wgt);

    static int smem_set = 0;
    if (!smem_set) {
        cudaFuncSetAttribute(conv3x3_tap_kernel,
                             cudaFuncAttributeMaxDynamicSharedMemorySize,
                             SMEM_BYTES);
        smem_set = 1;
    }
    dim3 grid(HW / 128, HW, 2);   // (2, 256, 2)
    conv3x3_tap_kernel<<<grid, NTHR, SMEM_BYTES>>>(bias, out);
}

// round 8
// speedup vs baseline: 6.1094x; 1.2573x over previous
#include <cuda_runtime.h>
#include <cuda_fp16.h>
#include <cstdint>

// Conv2d 3x3 pad1: x(128,256,256) * w(256,128,3,3) + b(256) -> out(256,256,256)
// Tap-decomposed implicit GEMM, mma.sync m16n8k16 fp16, 2-pass:
//   w*32 split into fp16 hi+lo (lo stays normal-range), x single fp16,
//   fp32 accumulate, epilogue multiplies by 1/32. R6-proven pipeline skeleton.

#define HW    256
#define CI    128
#define OC    256
#define NTHR  256
#define STR   80                    // smem row stride (64B data + 16B pad)
#define PLANE (130 * STR)           // 10400 B : one gy plane (130 gx rows)
#define A_BASE (3 * PLANE)          // 31200   : x is single fp16 (no lo split)
#define A_TILE 10240                // 128 oc rows x 80B
#define AOFF(buf, split) (A_BASE + (buf) * 2 * A_TILE + (split) * A_TILE)
#define SMEM_BYTES (A_BASE + 4 * A_TILE)   // 72160

// ---- global scratch (pre-converted fp16) ----
__device__ __half g_xh[HW * HW * CI];    // [y][x][ci]        x as fp16
__device__ __half g_wh[9 * OC * CI];     // [tap][oc][ci]     hi of w*32
__device__ __half g_wl[9 * OC * CI];     // [tap][oc][ci]     lo of w*32

__device__ __forceinline__ uint32_t s2u(const void* p) {
    uint32_t a;
    asm("{ .reg .u64 t; cvta.to.shared.u64 t, %1; cvt.u32.u64 %0, t; }"
        : "=r"(a) : "l"(p));
    return a;
}

#define CP16(sa, ga, sz)                                                   \
    asm volatile("cp.async.cg.shared.global [%0], [%1], 16, %2;"           \
                 :: "r"(sa), "l"(ga), "r"(sz) : "memory")
#define CP_COMMIT()  asm volatile("cp.async.commit_group;" ::: "memory")
#define CP_WAIT0()   asm volatile("cp.async.wait_group 0;" ::: "memory")

#define LDM4(r0, r1, r2, r3, addr)                                         \
    asm volatile("ldmatrix.sync.aligned.m8n8.x4.shared.b16 "               \
                 "{%0,%1,%2,%3}, [%4];"                                    \
                 : "=r"(r0), "=r"(r1), "=r"(r2), "=r"(r3) : "r"(addr))

#define MMA(d, a, b)                                                       \
    asm volatile("mma.sync.aligned.m16n8k16.row.col.f32.f16.f16.f32 "      \
                 "{%0,%1,%2,%3}, {%4,%5,%6,%7}, {%8,%9}, {%0,%1,%2,%3};"   \
                 : "+f"((d)[0]), "+f"((d)[1]), "+f"((d)[2]), "+f"((d)[3])  \
                 : "r"((a)[0]), "r"((a)[1]), "r"((a)[2]), "r"((a)[3]),     \
                   "r"((b)[0]), "r"((b)[1]))

// ================= pre-pass: x CHW fp32 -> HWC fp16 ========================
__global__ __launch_bounds__(256)
void prep_x_kernel(const float* __restrict__ x)
{
    __shared__ float sx[CI * 65];
    const int tid = threadIdx.x;
    const int px0 = blockIdx.x * 64;
    const int y   = blockIdx.y;

#pragma unroll
    for (int it = 0; it < 32; it++) {
        const int idx = it * 256 + tid;
        const int ci  = idx >> 6;
        const int px  = idx & 63;
        sx[ci * 65 + px] = x[ci * (HW * HW) + y * HW + px0 + px];
    }
    __syncthreads();

#pragma unroll
    for (int it = 0; it < 8; it++) {
        const int idx = it * 256 + tid;
        const int px  = idx >> 5;
        const int ci  = (idx & 31) * 4;
        ushort4 h;
        h.x = __half_as_ushort(__float2half(sx[(ci + 0) * 65 + px]));
        h.y = __half_as_ushort(__float2half(sx[(ci + 1) * 65 + px]));
        h.z = __half_as_ushort(__float2half(sx[(ci + 2) * 65 + px]));
        h.w = __half_as_ushort(__float2half(sx[(ci + 3) * 65 + px]));
        *(ushort4*)(g_xh + (size_t)(y * HW + px0 + px) * CI + ci) = h;
    }
}

// ====== pre-pass: w (oc,ci,3,3) fp32 -> [tap][oc][ci] fp16 hi/lo of w*32 ===
__global__ __launch_bounds__(256)
void prep_w_kernel(const float* __restrict__ w)
{
    const int o = blockIdx.x * 256 + threadIdx.x;   // 9*256*128 = 294912
    const int tap = o >> 15;
    const int oc  = (o >> 7) & 255;
    const int ci  = o & 127;
    const float v = w[(oc * CI + ci) * 9 + tap] * 32.0f;
    const __half hb = __float2half(v);
    g_wh[o] = hb;
    g_wl[o] = __float2half(v - __half2float(hb));
}

// =========================== main GEMM kernel ===============================
__global__ __launch_bounds__(NTHR, 2)
void conv3x3_tap_kernel(const float* __restrict__ bias,
                        float* __restrict__ out)
{
    extern __shared__ __align__(16) char smem[];
    const uint32_t sb = s2u(smem);

    const int tid  = threadIdx.x;
    const int lane = tid & 31;
    const int wid  = tid >> 5;
    const int wm   = wid >> 2;        // 0..1 : 64-oc warp tile
    const int wn   = wid & 3;         // 0..3 : 32-px warp tile

    const int x0  = blockIdx.x * 128;
    const int y   = blockIdx.y;
    const int oc0 = blockIdx.z * 128;

    const int a_row = lane & 15;
    const int a_kh  = lane >> 4;
    const int b_n   = (lane & 7) | ((lane >> 4) << 3);
    const int b_kh  = (lane >> 3) & 1;

    float acc[4][4][4];
#pragma unroll
    for (int i = 0; i < 4; i++)
#pragma unroll
        for (int j = 0; j < 4; j++)
#pragma unroll
            for (int q = 0; q < 4; q++) acc[i][j][q] = 0.0f;

#pragma unroll 1
    for (int cb = 0; cb < 4; cb++) {
        const int ci0 = cb * 32;

        // ---- stage x chunk: 3 planes x 130 rows x 32 ci (fp16) ----
#pragma unroll 1
        for (int i = tid; i < 1560; i += NTHR) {      // 390 rows x 4 x 16B
            const int q   = i & 3;
            const int row = i >> 2;                    // 0..389
            const int ky  = row / 130;
            const int gxl = row - ky * 130;
            const int gy  = y + ky - 1;
            const int gx  = x0 + gxl - 1;
            const uint32_t ok =
                ((unsigned)gy < (unsigned)HW && (unsigned)gx < (unsigned)HW)
                ? 16u : 0u;
            const int gyc = ok ? gy : 0;
            const int gxc = ok ? gx : 0;
            const size_t go = ((size_t)(gyc * HW + gxc) * CI + ci0) * 2 + q * 16;
            CP16(sb + ky * PLANE + gxl * STR + q * 16, (const char*)g_xh + go, ok);
        }
        // ---- stage A tap 0 into buf 0 (hi + lo) ----
#pragma unroll 1
        for (int i = tid; i < 1024; i += NTHR) {
            const int split = i >> 9;
            const int r2    = i & 511;
            const int oc    = r2 >> 2;
            const int q     = r2 & 3;
            const __half* src = split ? g_wl : g_wh;
            const size_t go = ((size_t)(oc0 + oc) * CI + ci0) * 2 + q * 16;
            CP16(sb + AOFF(0, split) + oc * STR + q * 16,
                 (const char*)src + go, 16u);
        }
        CP_COMMIT();
        CP_WAIT0();
        __syncthreads();

#pragma unroll 1
        for (int tap = 0; tap < 9; tap++) {
            // prefetch next tap's A into the other buffer
            if (tap < 8) {
                const int nb = (tap + 1) & 1;
#pragma unroll 1
                for (int i = tid; i < 1024; i += NTHR) {
                    const int split = i >> 9;
                    const int r2    = i & 511;
                    const int oc    = r2 >> 2;
                    const int q     = r2 & 3;
                    const __half* src = split ? g_wl : g_wh;
                    const size_t go =
                        ((size_t)((tap + 1) * OC + oc0 + oc) * CI + ci0) * 2
                        + q * 16;
                    CP16(sb + AOFF(nb, split) + oc * STR + q * 16,
                         (const char*)src + go, 16u);
                }
                CP_COMMIT();
            }

            // ---- compute this tap (2 k16 steps, 2 passes: hi, lo) ----
            const int ky = tap / 3;
            const int kx = tap - ky * 3;
            const int ab = tap & 1;
            const uint32_t xbase = sb + ky * PLANE + kx * STR;

#pragma unroll
            for (int ks = 0; ks < 2; ks++) {
                uint32_t ah[4][4], al[4][4], bh[2][4];

#pragma unroll
                for (int mf = 0; mf < 4; mf++) {
                    const uint32_t ao =
                        (uint32_t)((wm * 64 + mf * 16 + a_row) * STR
                                   + ks * 32 + a_kh * 16);
                    LDM4(ah[mf][0], ah[mf][1], ah[mf][2], ah[mf][3],
                         sb + AOFF(ab, 0) + ao);
                    LDM4(al[mf][0], al[mf][1], al[mf][2], al[mf][3],
                         sb + AOFF(ab, 1) + ao);
                }
#pragma unroll
                for (int bp = 0; bp < 2; bp++) {
                    const uint32_t bo =
                        (uint32_t)((wn * 32 + bp * 16 + b_n) * STR
                                   + ks * 32 + b_kh * 16);
                    LDM4(bh[bp][0], bh[bp][1], bh[bp][2], bh[bp][3],
                         xbase + bo);
                }
#pragma unroll
                for (int mf = 0; mf < 4; mf++)
#pragma unroll
                    for (int nf = 0; nf < 4; nf++) {
                        uint32_t bf[2] = { bh[nf >> 1][(nf & 1) * 2 + 0],
                                           bh[nf >> 1][(nf & 1) * 2 + 1] };
                        MMA(acc[mf][nf], ah[mf], bf);
                        MMA(acc[mf][nf], al[mf], bf);
                    }
            }

            if (tap < 8) {
                CP_WAIT0();
                __syncthreads();
            }
        }
        __syncthreads();   // protect x tile before next chunk's staging
    }

    // ---- epilogue: acc/32 + bias -> out ----
    const float s = 0.03125f;
#pragma unroll
    for (int mf = 0; mf < 4; mf++) {
        const int ocb = oc0 + wm * 64 + mf * 16 + (lane >> 2);
        const float bv0 = bias[ocb];
        const float bv1 = bias[ocb + 8];
#pragma unroll
        for (int nf = 0; nf < 4; nf++) {
            const int px = wn * 32 + nf * 8 + (lane & 3) * 2;
            float* p0 = out + (size_t)ocb * (HW * HW) + (size_t)y * HW + x0 + px;
            float2 v0 = make_float2(fmaf(acc[mf][nf][0], s, bv0),
                                    fmaf(acc[mf][nf][1], s, bv0));
            float2 v1 = make_float2(fmaf(acc[mf][nf][2], s, bv1),
                                    fmaf(acc[mf][nf][3], s, bv1));
            *(float2*)p0 = v0;
            *(float2*)(p0 + 8 * (HW * HW)) = v1;
        }
    }
}

extern "C" void kernel_launch(void* const* d_in, const int* in_sizes, int n_in,
                              void* d_out, int out_size)
{
    const float* x    = (const float*)d_in[0];   // (128,256,256)
    const float* wgt  = (const float*)d_in[1];   // (256,128,3,3)
    const float* bias = (const float*)d_in[2];   // (256,1,1)
    float* out = (float*)d_out;                  // (256,256,256)

    prep_x_kernel<<<dim3(HW / 64, HW), 256>>>(x);
    prep_w_kernel<<<dim3(9 * OC * CI / 256), 256>>>(wgt);

    static int smem_set = 0;
    if (!smem_set) {
        cudaFuncSetAttribute(conv3x3_tap_kernel,
                             cudaFuncAttributeMaxDynamicSharedMemorySize,
                             SMEM_BYTES);
        smem_set = 1;
    }
    dim3 grid(HW / 128, HW, 2);   // (2, 256, 2)
    conv3x3_tap_kernel<<<grid, NTHR, SMEM_BYTES>>>(bias, out);
}